// round 6
// baseline (speedup 1.0000x reference)
#include <cuda_runtime.h>
#include <cstdint>
#include <cstddef>

// Diverse beam search step:
//   B=128 batches, K=16 beams, V=50257 vocab, T=20, H=512, state (2,2,B,K,H)
// Outputs concatenated into float d_out:
//   [0      , 40960 )  new_beam_seq      [B,T,K]  (tokens as float)
//   [40960  , 81920 )  new_beam_seq_lp   [B,T,K]
//   [81920  , 83968 )  sel_p             [B,K]
//   [83968  , end   )  new_state         [2,2,B,K,H]

#define B_DIM   128
#define K_DIM   16
#define V_DIM   50257
#define T_DIM   20
#define H_DIM   512
#define VPAD    (V_DIM + 527)      // padded penalty array (multiple of 4)
#define NMARK   ((VPAD >> 5) + 4)  // bitmap words (+straddle pad)
#define NTHREADS 512
#define FULLMASK 0xffffffffu

struct SmemLayout {
    float    pen[VPAD];            // dense penalty (diversity + EOS), sparse content
    unsigned mark[NMARK];          // bit v set <=> pen[v] != 0
    float wval[K_DIM][16];         // per-warp(beam) top-16 aug values, sorted desc
    int   widx[K_DIM][16];         // matching vocab ids
    float ssel[K_DIM];             // selected candidate total logprobs
    int   sq[K_DIM];               // source beam per selected slot
    int   stok[K_DIM];             // chosen token
    float sr[K_DIM];               // unaugmented local logprob
    int   seq64;                   // 1 if beam_seq ints are int64
    int   prev64;                  // 1 if prev_decisions ints are int64
};

// Maintain top-16 sorted by (value desc, index asc) — matches jax.lax.top_k ties.
__device__ __forceinline__ void insert16(float* val, int* idx, float a, int v) {
    if (!(a > val[15] || (a == val[15] && v < idx[15]))) return;
    int pos = 15;
    while (pos > 0 && (val[pos - 1] < a || (val[pos - 1] == a && idx[pos - 1] > v))) {
        val[pos] = val[pos - 1];
        idx[pos] = idx[pos - 1];
        --pos;
    }
    val[pos] = a;
    idx[pos] = v;
}

__device__ __forceinline__ long long read_tok(const void* p, size_t i, int is64) {
    return is64 ? ((const long long*)p)[i] : (long long)((const int*)p)[i];
}

// Warp-cooperative int-width sniff: int64 tokens < 2^31 => every odd 32-bit
// word is 0 (LE). Checks first 512 words (256 candidate odd words).
__device__ __forceinline__ int sniff64_warp(const void* p, int lane) {
    const unsigned* wptr = (const unsigned*)p;
    unsigned nz = 0;
    #pragma unroll
    for (int k = 0; k < 8; ++k) nz |= wptr[1 + 2 * (lane + 32 * k)];
    return __any_sync(FULLMASK, nz != 0) ? 0 : 1;
}

__global__ void __launch_bounds__(NTHREADS, 1)
beam_step_kernel(const float* __restrict__ logprobs,   // [B,K,V]
                 const void*  __restrict__ beam_seq,   // [B,T,K] int32/int64
                 const float* __restrict__ beam_lp,    // [B,T,K]
                 const float* __restrict__ bsum,       // [B,K]
                 const float* __restrict__ state,      // [2,2,B,K,H]
                 const void*  __restrict__ prev,       // [B,nprev] int32/int64
                 const int*   __restrict__ tptr,       // scalar t
                 float*       __restrict__ out,
                 int nprev)
{
    extern __shared__ char smraw[];
    SmemLayout& s = *reinterpret_cast<SmemLayout*>(smraw);

    const int b    = blockIdx.x;
    const int tid  = threadIdx.x;
    const int w    = tid >> 5;     // warp id == beam id
    const int lane = tid & 31;

    // ---- phase 0: zero penalty + bitmap (vectorized); detect int widths ----
    {
        float4* pz = (float4*)s.pen;
        for (int v = tid; v < (VPAD >> 2); v += NTHREADS)
            pz[v] = make_float4(0.f, 0.f, 0.f, 0.f);
        for (int v = tid; v < NMARK; v += NTHREADS) s.mark[v] = 0u;
    }
    if (w == 0) {
        int r = sniff64_warp(beam_seq, lane);
        if (lane == 0) s.seq64 = r;
    } else if (w == 1) {
        int r = sniff64_warp(prev, lane);
        if (lane == 0) s.prev64 = r;
    }
    __syncthreads();
    const int seq64  = s.seq64;
    const int prev64 = s.prev64;

    // ---- phase 1: diversity counts (0.5/occurrence) + EOS penalty + bitmap ----
    for (int i = tid; i < nprev; i += NTHREADS) {
        size_t gi = (size_t)b * nprev + i;
        int tok = (int)read_tok(prev, gi, prev64);
        if ((unsigned)tok < (unsigned)V_DIM) {   // guard smem vs bad sniff/token
            atomicAdd(&s.pen[tok], 0.5f);
            atomicOr(&s.mark[tok >> 5], 1u << (tok & 31));
        }
    }
    if (lane < 16) { s.wval[w][lane] = -INFINITY; s.widx[w][lane] = 0x7fffffff; }
    __syncthreads();
    if (tid == 0) {
        s.pen[V_DIM - 1] += 1000.0f;
        atomicOr(&s.mark[(V_DIM - 1) >> 5], 1u << ((V_DIM - 1) & 31));
    }
    __syncthreads();

    // ---- phase 2: per-beam top-16 of aug = lp - pen, one warp per beam ----
    float* lv = s.wval[w];
    int*   li = s.widx[w];
    const size_t r0 = ((size_t)b * K_DIM + w) * V_DIM;
    const float* row = logprobs + r0;

    const int off0  = (int)((4 - (r0 & 3)) & 3);          // head peel count
    const int tailc = (int)((r0 + V_DIM) & 3);            // tail peel count
    const int a1    = V_DIM - tailc;                      // end of aligned region
    const int n4    = (a1 - off0) >> 2;                   // float4 count
    const float4* p4 = (const float4*)(row + off0);

    if (lane == 0) {
        for (int v = 0; v < off0; ++v) insert16(lv, li, row[v] - s.pen[v], v);
        for (int v = a1; v < V_DIM; ++v) insert16(lv, li, row[v] - s.pen[v], v);
    }
    __syncwarp();
    float th = lv[15];

    const float4 NEG4 = make_float4(-INFINITY, -INFINITY, -INFINITY, -INFINITY);

    // 2-stage software pipeline: prefetch next 4 float4s while processing current.
    float4 xp[4];
    #pragma unroll
    for (int u = 0; u < 4; ++u) {
        const int iu = 32 * u + lane;
        xp[u] = (iu < n4) ? __ldcs(p4 + iu) : NEG4;
    }

    for (int base4 = 0; base4 < n4; base4 += 128) {       // 512 floats / warp-iter
        float4 xc[4];
        #pragma unroll
        for (int u = 0; u < 4; ++u) xc[u] = xp[u];

        const int nb = base4 + 128;
        if (nb < n4) {
            #pragma unroll
            for (int u = 0; u < 4; ++u) {
                const int iu = nb + 32 * u + lane;        // coalesced: warp covers 512B
                xp[u] = (iu < n4) ? __ldcs(p4 + iu) : NEG4;
            }
        }

        float a[16];
        int   av[4];
        #pragma unroll
        for (int u = 0; u < 4; ++u) {
            const int iu = base4 + 32 * u + lane;
            const int vu = off0 + 4 * iu;
            av[u] = (iu < n4) ? vu : 0x7ffffff0;
            float4 x = xc[u];
            if (iu < n4) {
                // sparse-penalty bitmap lookup (2 words cover any 4-bit straddle)
                const int wi = vu >> 5;
                unsigned long long um =
                    (unsigned long long)s.mark[wi] |
                    ((unsigned long long)s.mark[wi + 1] << 32);
                unsigned bits = (unsigned)((um >> (vu & 31)) & 0xFu);
                if (bits) {
                    if (bits & 1u) x.x -= s.pen[vu + 0];
                    if (bits & 2u) x.y -= s.pen[vu + 1];
                    if (bits & 4u) x.z -= s.pen[vu + 2];
                    if (bits & 8u) x.w -= s.pen[vu + 3];
                }
            }
            a[4 * u + 0] = x.x; a[4 * u + 1] = x.y;
            a[4 * u + 2] = x.z; a[4 * u + 3] = x.w;
        }

        float mx = a[0];
        #pragma unroll
        for (int c = 1; c < 16; ++c) mx = fmaxf(mx, a[c]);

        unsigned m = __ballot_sync(FULLMASK, mx > th || (mx == th && mx > -INFINITY));
        if (m) {
            for (int src = 0; src < 32; ++src) {
                if ((m >> src) & 1u) {
                    if (lane == src) {
                        #pragma unroll
                        for (int u = 0; u < 4; ++u)
                            #pragma unroll
                            for (int c = 0; c < 4; ++c)
                                insert16(lv, li, a[4 * u + c], av[u] + c);
                    }
                    __syncwarp();
                }
            }
            th = lv[15];
        }
    }
    __syncthreads();

    // ---- phase 3: global top-16 over 256 candidates (warp 0), stable ties ----
    if (w == 0) {
        float cv[8];
        #pragma unroll
        for (int u = 0; u < 8; ++u) {
            int f = lane + 32 * u;
            cv[u] = __ldg(&bsum[b * K_DIM + (f >> 4)]) + s.wval[f >> 4][f & 15];
        }
        for (int r = 0; r < 16; ++r) {
            float bv = -INFINITY; int bf = 1 << 30;
            #pragma unroll
            for (int u = 0; u < 8; ++u) {            // ascending f => strict > keeps min f
                int f = lane + 32 * u;
                if (cv[u] > bv) { bv = cv[u]; bf = f; }
            }
            #pragma unroll
            for (int o = 16; o > 0; o >>= 1) {
                float ov = __shfl_down_sync(FULLMASK, bv, o);
                int   of = __shfl_down_sync(FULLMASK, bf, o);
                if (ov > bv || (ov == bv && of < bf)) { bv = ov; bf = of; }
            }
            bv = __shfl_sync(FULLMASK, bv, 0);
            bf = __shfl_sync(FULLMASK, bf, 0);
            if (lane == 0) {
                s.ssel[r] = bv;
                s.sq[r]   = bf >> 4;
                s.stok[r] = s.widx[bf >> 4][bf & 15];
            }
            if ((bf & 31) == lane) cv[bf >> 5] = -INFINITY;   // remove selected
        }
        __syncwarp();
        if (lane < 16) {
            int q   = s.sq[lane];
            int tok = s.stok[lane];
            float rr = __ldg(&logprobs[((size_t)b * K_DIM + q) * V_DIM + tok]);
            if (tok == V_DIM - 1) rr -= 1000.0f;   // unaug includes EOS penalty only
            s.sr[lane] = rr;
        }
    }
    __syncthreads();

    // ---- phase 4: write outputs ----
    int ti = *tptr;                                  // int32/int64 LE low word
    if (ti < 1 || ti >= T_DIM) ti = (int)__int_as_float(ti);  // float fallback

    const size_t OFF1 = (size_t)B_DIM * T_DIM * K_DIM;        // 40960
    const size_t OFF2 = OFF1 * 2;                             // 81920
    const size_t OFF3 = OFF2 + (size_t)B_DIM * K_DIM;         // 83968

    for (int e = tid; e < T_DIM * K_DIM; e += NTHREADS) {
        const int i = e >> 4, k = e & 15;
        const size_t oidx = ((size_t)b * T_DIM + i) * K_DIM + k;
        float tokf, lpf;
        if (i < ti) {
            size_t gidx = ((size_t)b * T_DIM + i) * K_DIM + s.sq[k];
            tokf = (float)read_tok(beam_seq, gidx, seq64);
            lpf  = beam_lp[gidx];
        } else if (i == ti) {
            tokf = (float)s.stok[k];
            lpf  = s.sr[k];
        } else {
            tokf = (float)read_tok(beam_seq, oidx, seq64);
            lpf  = beam_lp[oidx];
        }
        out[oidx]        = tokf;
        out[OFF1 + oidx] = lpf;
    }
    if (tid < K_DIM) out[OFF2 + (size_t)b * K_DIM + tid] = s.ssel[tid];

    // state gather along beam dim, float4-vectorized (H=512 => 128 float4)
    const float4* st4 = (const float4*)state;
    float4* o4 = (float4*)(out + OFF3);
    for (int e = tid; e < 4 * K_DIM * (H_DIM / 4); e += NTHREADS) {  // 8192
        const int h4 = e & 127;
        const int k  = (e >> 7) & 15;
        const int sl = e >> 11;                      // s*2 + l in [0,4)
        const size_t ibase = ((size_t)sl * B_DIM + b) * K_DIM;
        o4[(ibase + k) * 128 + h4] = __ldcs(&st4[(ibase + s.sq[k]) * 128 + h4]);
    }
}

extern "C" void kernel_launch(void* const* d_in, const int* in_sizes, int n_in,
                              void* d_out, int out_size) {
    const float* logprobs = (const float*)d_in[0];
    const void*  beam_seq = d_in[1];
    const float* beam_lp  = (const float*)d_in[2];
    const float* bsum     = (const float*)d_in[3];
    const float* state    = (const float*)d_in[4];
    const void*  prev     = d_in[5];
    const int*   tptr     = (const int*)d_in[6];
    const int    nprev    = in_sizes[5] / B_DIM;     // 256

    const size_t smem = sizeof(SmemLayout);
    cudaFuncSetAttribute(beam_step_kernel,
                         cudaFuncAttributeMaxDynamicSharedMemorySize, (int)smem);
    beam_step_kernel<<<B_DIM, NTHREADS, smem>>>(
        logprobs, beam_seq, beam_lp, bsum, state, prev, tptr,
        (float*)d_out, nprev);
}